// round 7
// baseline (speedup 1.0000x reference)
#include <cuda_runtime.h>
#include <cuda_bf16.h>
#include <cstdint>

#define NN 4096
#define DD 512
#define NTILE 32        // NN / 128
#define NBLK  528       // NTILE*(NTILE+1)/2
#define STR   72        // smem row stride in bf16 (64 + 8 pad) -> 144 B, 16B aligned

static __device__ __nv_bfloat16 g_w[NN * DD];   // normalized * sqrt(10), bf16
static __device__ float g_S[NN];                // sum_j!=i exp(sim_ij)
static __device__ float g_P[NN];                // sum_{same label, j!=i} sim_ij
static __device__ int   g_lab[NN];
static __device__ int   g_cnt[128];

// ---------------------------------------------------------------------------
__global__ void zero_kernel() {
    int i = blockIdx.x * blockDim.x + threadIdx.x;
    if (i < NN) { g_S[i] = 0.f; g_P[i] = 0.f; }
    if (i < 128) g_cnt[i] = 0;
}

// Labels: dtype-agnostic extraction. View buffer as int32 (always in-bounds).
// If the true dtype is int64 (little-endian, values < 2^31), every odd 32-bit
// word is 0; with int32 labels uniform in [0,100), 32 consecutive odd-position
// zeros is ~impossible. Each block redundantly detects, then extracts.
__global__ void label_kernel(const int* __restrict__ lab32) {
    __shared__ int nz;
    if (threadIdx.x == 0) nz = 0;
    __syncthreads();
    if (threadIdx.x < 64 && (threadIdx.x & 1) && lab32[threadIdx.x] != 0)
        atomicAdd(&nz, 1);
    __syncthreads();
    bool is64 = (nz == 0);
    int i = blockIdx.x * blockDim.x + threadIdx.x;
    if (i < NN) g_lab[i] = is64 ? lab32[2 * i] : lab32[i];
}

// one block (128 threads) per row: norm + normalize + bf16
__global__ void norm_kernel(const float* __restrict__ x) {
    int row = blockIdx.x;
    int tid = threadIdx.x;
    const float* xr = x + row * DD;
    float v[4];
    float s = 0.f;
#pragma unroll
    for (int k = 0; k < 4; k++) { v[k] = xr[tid + 128 * k]; s += v[k] * v[k]; }
#pragma unroll
    for (int m = 16; m; m >>= 1) s += __shfl_xor_sync(0xffffffffu, s, m);
    __shared__ float ws[4];
    if ((tid & 31) == 0) ws[tid >> 5] = s;
    __syncthreads();
    float tot = ws[0] + ws[1] + ws[2] + ws[3];
    float scale = sqrtf(10.f) * rsqrtf(tot);
#pragma unroll
    for (int k = 0; k < 4; k++)
        g_w[row * DD + tid + 128 * k] = __float2bfloat16(v[k] * scale);
}

__global__ void hist_kernel() {
    int i = blockIdx.x * blockDim.x + threadIdx.x;
    if (i < NN) atomicAdd(&g_cnt[g_lab[i] & 127], 1);  // mask: IMA-proof
}

// ---------------------------------------------------------------------------
// Fused symmetric GEMM + SupCon epilogue.
// Block tile 128x128, only upper-triangular tile pairs (bi <= bj).
// 256 threads = 8 warps, warp grid 4(M) x 2(N): warp strip 32(M) x 64(N).
// mma.sync.m16n8k16 row.col f32.bf16 -> computes W * W^T directly.
__global__ __launch_bounds__(256) void gemm_kernel() {
    __shared__ __align__(16) __nv_bfloat16 As[128 * STR];
    __shared__ __align__(16) __nv_bfloat16 Bs[128 * STR];

    // triangular decode of blockIdx.x -> (bi, bj), bi <= bj
    int b = blockIdx.x;
    int bi = 0;
    while (b >= NTILE - bi) { b -= NTILE - bi; bi++; }
    int bj = bi + b;
    const int iBase = bi * 128, jBase = bj * 128;
    const bool diagTile = (bi == bj);

    const int tid = threadIdx.x;
    const int warp = tid >> 5, lane = tid & 31;
    const int wm = warp >> 1, wn = warp & 1;     // warp M 0..3, warp N 0..1
    const int qr = lane >> 2, qc = lane & 3;     // quad row / col

    float acc[2][8][4];
#pragma unroll
    for (int mt = 0; mt < 2; mt++)
#pragma unroll
        for (int nt = 0; nt < 8; nt++)
#pragma unroll
            for (int c = 0; c < 4; c++) acc[mt][nt][c] = 0.f;

    // ldmatrix per-lane addressing (byte offsets within tile row stride 144B)
    // A x4 tiles in frag order (r,k),(r+8,k),(r,k+8),(r+8,k+8)
    const int aRow  = wm * 32 + (lane & 7) + ((lane >> 3) & 1) * 8;
    const int aColB = ((lane >> 4) & 1) * 16;
    // B x4 tiles in order (n,k),(n,k+8),(n+8,k),(n+8,k+8) -> b0lo,b1lo,b0hi,b1hi
    const int bRow  = wn * 64 + (lane & 7) + ((lane >> 4) & 1) * 8;
    const int bColB = ((lane >> 3) & 1) * 16;

    const uint32_t aBase = (uint32_t)__cvta_generic_to_shared(As);
    const uint32_t bBase = (uint32_t)__cvta_generic_to_shared(Bs);

    for (int k0 = 0; k0 < DD; k0 += 64) {
        __syncthreads();
#pragma unroll
        for (int r = 0; r < 4; r++) {
            int idx = tid + 256 * r;
            int row = idx >> 3, c8 = idx & 7;
            *(float4*)&As[row * STR + c8 * 8] =
                *(const float4*)&g_w[(iBase + row) * DD + k0 + c8 * 8];
            *(float4*)&Bs[row * STR + c8 * 8] =
                *(const float4*)&g_w[(jBase + row) * DD + k0 + c8 * 8];
        }
        __syncthreads();

#pragma unroll
        for (int kk = 0; kk < 64; kk += 16) {
            uint32_t a[2][4], bb[4][4];
#pragma unroll
            for (int mt = 0; mt < 2; mt++) {
                uint32_t addr = aBase + (uint32_t)((aRow + mt * 16) * (STR * 2) + kk * 2 + aColB);
                asm volatile(
                    "ldmatrix.sync.aligned.m8n8.x4.shared.b16 {%0,%1,%2,%3}, [%4];"
                    : "=r"(a[mt][0]), "=r"(a[mt][1]), "=r"(a[mt][2]), "=r"(a[mt][3])
                    : "r"(addr));
            }
#pragma unroll
            for (int np = 0; np < 4; np++) {
                uint32_t addr = bBase + (uint32_t)((bRow + np * 16) * (STR * 2) + kk * 2 + bColB);
                asm volatile(
                    "ldmatrix.sync.aligned.m8n8.x4.shared.b16 {%0,%1,%2,%3}, [%4];"
                    : "=r"(bb[np][0]), "=r"(bb[np][1]), "=r"(bb[np][2]), "=r"(bb[np][3])
                    : "r"(addr));
            }
#pragma unroll
            for (int mt = 0; mt < 2; mt++)
#pragma unroll
                for (int nt = 0; nt < 8; nt++) {
                    int np = nt >> 1, hi = nt & 1;
                    uint32_t b0 = bb[np][hi ? 2 : 0], b1 = bb[np][hi ? 3 : 1];
                    asm volatile(
                        "mma.sync.aligned.m16n8k16.row.col.f32.bf16.bf16.f32 "
                        "{%0,%1,%2,%3},{%4,%5,%6,%7},{%8,%9},{%0,%1,%2,%3};"
                        : "+f"(acc[mt][nt][0]), "+f"(acc[mt][nt][1]),
                          "+f"(acc[mt][nt][2]), "+f"(acc[mt][nt][3])
                        : "r"(a[mt][0]), "r"(a[mt][1]), "r"(a[mt][2]), "r"(a[mt][3]),
                          "r"(b0), "r"(b1));
                }
        }
    }

    // ---- fused epilogue ----
    __syncthreads();
    int* labI = (int*)As;
    int* labJ = (int*)Bs;
    if (tid < 128) { labI[tid] = g_lab[iBase + tid]; labJ[tid] = g_lab[jBase + tid]; }
    __syncthreads();

    float colE[16], colP[16];
#pragma unroll
    for (int c = 0; c < 16; c++) { colE[c] = 0.f; colP[c] = 0.f; }

#pragma unroll
    for (int mt = 0; mt < 2; mt++) {
#pragma unroll
        for (int h = 0; h < 2; h++) {
            int iLoc = wm * 32 + mt * 16 + qr + h * 8;
            int gi = iBase + iLoc;
            int li = labI[iLoc];
            float rE = 0.f, rP = 0.f;
#pragma unroll
            for (int nt = 0; nt < 8; nt++) {
#pragma unroll
                for (int cc = 0; cc < 2; cc++) {
                    int jLoc = wn * 64 + nt * 8 + qc * 2 + cc;
                    int gj = jBase + jLoc;
                    float s = acc[mt][nt][h * 2 + cc];
                    if (gi != gj) {
                        float e = __expf(s);
                        float ps = (li == labJ[jLoc]) ? s : 0.f;
                        rE += e; rP += ps;
                        if (!diagTile) { colE[nt * 2 + cc] += e; colP[nt * 2 + cc] += ps; }
                    }
                }
            }
            // reduce over qc (4 lanes share a row)
            rE += __shfl_xor_sync(0xffffffffu, rE, 1);
            rE += __shfl_xor_sync(0xffffffffu, rE, 2);
            rP += __shfl_xor_sync(0xffffffffu, rP, 1);
            rP += __shfl_xor_sync(0xffffffffu, rP, 2);
            if (qc == 0) {
                atomicAdd(&g_S[gi], rE);
                atomicAdd(&g_P[gi], rP);
            }
        }
    }

    if (!diagTile) {
        // mirrored contributions: sim_ji = sim_ij -> reduce over qr (8 lanes share a col)
#pragma unroll
        for (int nt = 0; nt < 8; nt++) {
#pragma unroll
            for (int cc = 0; cc < 2; cc++) {
                float e = colE[nt * 2 + cc], p = colP[nt * 2 + cc];
                e += __shfl_xor_sync(0xffffffffu, e, 4);
                e += __shfl_xor_sync(0xffffffffu, e, 8);
                e += __shfl_xor_sync(0xffffffffu, e, 16);
                p += __shfl_xor_sync(0xffffffffu, p, 4);
                p += __shfl_xor_sync(0xffffffffu, p, 8);
                p += __shfl_xor_sync(0xffffffffu, p, 16);
                if (lane < 4) {
                    int gj = jBase + wn * 64 + nt * 8 + lane * 2 + cc;
                    atomicAdd(&g_S[gj], e);
                    atomicAdd(&g_P[gj], p);
                }
            }
        }
    }
}

// ---------------------------------------------------------------------------
__global__ void fin_kernel(float* __restrict__ out) {
    __shared__ float sm[512];
    int tid = threadIdx.x;
    float s = 0.f;
    for (int i = tid; i < NN; i += 512) {
        float C = (float)(g_cnt[g_lab[i] & 127] - 1);
        float v = (g_P[i] - C * logf(g_S[i])) / (C + 1e-8f);
        s += v;
    }
    sm[tid] = s;
    __syncthreads();
    for (int st = 256; st; st >>= 1) {
        if (tid < st) sm[tid] += sm[tid + st];
        __syncthreads();
    }
    if (tid == 0) out[0] = -sm[0] / (float)NN;
}

// ---------------------------------------------------------------------------
extern "C" void kernel_launch(void* const* d_in, const int* in_sizes, int n_in,
                              void* d_out, int out_size) {
    const float* features = (const float*)d_in[0];
    const int* labels32 = (const int*)d_in[1];   // int32 view; layout auto-detected
    float* out = (float*)d_out;

    zero_kernel<<<16, 256>>>();
    label_kernel<<<16, 256>>>(labels32);
    norm_kernel<<<NN, 128>>>(features);
    hist_kernel<<<16, 256>>>();
    gemm_kernel<<<NBLK, 256>>>();
    fin_kernel<<<1, 512>>>(out);
}

// round 9
// speedup vs baseline: 1.0202x; 1.0202x over previous
#include <cuda_runtime.h>
#include <cuda_bf16.h>
#include <cstdint>

#define NN 4096
#define DD 512
#define NTILE 32        // NN / 128
#define NBLK  528       // NTILE*(NTILE+1)/2
#define BK    64        // k-slab width in bf16
#define STR   72        // smem row stride in bf16 (64 + 8 pad) -> 144 B
#define STAGE_B (128 * STR * 2)          // bytes per tile stage (18432)
#define SMEM_DYN (4 * STAGE_B)           // A,B x 2 stages = 73728 B

static __device__ __nv_bfloat16 g_w[NN * DD];   // normalized * sqrt(10), bf16
static __device__ float g_S[NN];                // sum_j!=i exp(sim_ij)
static __device__ float g_P[NN];                // sum_{same label, j!=i} sim_ij
static __device__ int   g_lab[NN];

// ---------------------------------------------------------------------------
__device__ __forceinline__ void cp_async16(uint32_t dst, const void* src) {
    asm volatile("cp.async.cg.shared.global [%0], [%1], 16;"
                 :: "r"(dst), "l"(src) : "memory");
}

// ---------------------------------------------------------------------------
// Fused prep: per-row zero of S/P + label extraction (dtype-agnostic) + norm.
// Labels buffer viewed as int32 (in-bounds for either dtype). If true dtype is
// int64 (LE, values < 2^31), all odd 32-bit words are 0; with int32 labels in
// [0,100) that's ~impossible over 32 samples.
__global__ void norm_kernel(const float* __restrict__ x,
                            const int* __restrict__ lab32) {
    int row = blockIdx.x;
    int tid = threadIdx.x;
    __shared__ int nz;
    if (tid == 0) nz = 0;
    __syncthreads();
    if (tid < 64 && (tid & 1) && lab32[tid] != 0) atomicAdd(&nz, 1);

    const float* xr = x + row * DD;
    float v[4];
    float s = 0.f;
#pragma unroll
    for (int k = 0; k < 4; k++) { v[k] = xr[tid + 128 * k]; s += v[k] * v[k]; }
#pragma unroll
    for (int m = 16; m; m >>= 1) s += __shfl_xor_sync(0xffffffffu, s, m);
    __shared__ float ws[4];
    if ((tid & 31) == 0) ws[tid >> 5] = s;
    __syncthreads();
    float tot = ws[0] + ws[1] + ws[2] + ws[3];
    float scale = sqrtf(10.f) * rsqrtf(tot);
#pragma unroll
    for (int k = 0; k < 4; k++)
        g_w[row * DD + tid + 128 * k] = __float2bfloat16(v[k] * scale);

    if (tid == 0) {
        bool is64 = (nz == 0);
        g_lab[row] = is64 ? lab32[2 * row] : lab32[row];
        g_S[row] = 0.f;
        g_P[row] = 0.f;
    }
}

// ---------------------------------------------------------------------------
// Fused symmetric GEMM + SupCon epilogue (HMMA mma.sync path).
// Block tile 128x128, upper-triangular tile pairs only. 256 threads = 8 warps,
// warp grid 4(M) x 2(N). cp.async double-buffered smem pipeline over BK=64.
__global__ __launch_bounds__(256) void gemm_kernel() {
    extern __shared__ __align__(16) char dyn[];
    __nv_bfloat16* As = (__nv_bfloat16*)dyn;                 // [2][128*STR]
    __nv_bfloat16* Bs = As + 2 * 128 * STR;                  // [2][128*STR]

    // triangular decode of blockIdx.x -> (bi, bj), bi <= bj
    int b = blockIdx.x;
    int bi = 0;
    while (b >= NTILE - bi) { b -= NTILE - bi; bi++; }
    int bj = bi + b;
    const int iBase = bi * 128, jBase = bj * 128;
    const bool diagTile = (bi == bj);

    const int tid = threadIdx.x;
    const int warp = tid >> 5, lane = tid & 31;
    const int wm = warp >> 1, wn = warp & 1;     // warp M 0..3, warp N 0..1
    const int qr = lane >> 2, qc = lane & 3;     // quad row / col

    float acc[2][8][4];
#pragma unroll
    for (int mt = 0; mt < 2; mt++)
#pragma unroll
        for (int nt = 0; nt < 8; nt++)
#pragma unroll
            for (int c = 0; c < 4; c++) acc[mt][nt][c] = 0.f;

    // ldmatrix per-lane addressing (byte offsets within tile, row stride 144B)
    const int aRow  = wm * 32 + (lane & 7) + ((lane >> 3) & 1) * 8;
    const int aColB = ((lane >> 4) & 1) * 16;
    const int bRow  = wn * 64 + (lane & 7) + ((lane >> 4) & 1) * 8;
    const int bColB = ((lane >> 3) & 1) * 16;

    const uint32_t aBase0 = (uint32_t)__cvta_generic_to_shared(As);
    const uint32_t bBase0 = (uint32_t)__cvta_generic_to_shared(Bs);

    // per-thread staging coords: 256 threads x 4 rounds x 16B covers a stage
    const int ldRow = tid >> 3;          // 0..31 (+32 per round)
    const int ldC   = (tid & 7) * 16;    // byte col 0..112

    // issue cp.async for k-slab `it` into stage buffer (it & 1)
    auto issue = [&](int it) {
        const int k0 = it * BK;
        const uint32_t aDst = aBase0 + (uint32_t)((it & 1) * STAGE_B);
        const uint32_t bDst = bBase0 + (uint32_t)((it & 1) * STAGE_B);
        const __nv_bfloat16* aSrc = g_w + (size_t)(iBase + ldRow) * DD + k0 + (tid & 7) * 8;
        const __nv_bfloat16* bSrc = g_w + (size_t)(jBase + ldRow) * DD + k0 + (tid & 7) * 8;
#pragma unroll
        for (int r = 0; r < 4; r++) {
            int row = ldRow + 32 * r;
            cp_async16(aDst + row * (STR * 2) + ldC, aSrc + (size_t)(32 * r) * DD);
            cp_async16(bDst + row * (STR * 2) + ldC, bSrc + (size_t)(32 * r) * DD);
        }
        asm volatile("cp.async.commit_group;" ::: "memory");
    };

    issue(0);
    for (int it = 0; it < DD / BK; it++) {
        if (it + 1 < DD / BK) {
            issue(it + 1);
            asm volatile("cp.async.wait_group 1;" ::: "memory");
        } else {
            asm volatile("cp.async.wait_group 0;" ::: "memory");
        }
        __syncthreads();

        const uint32_t aB = aBase0 + (uint32_t)((it & 1) * STAGE_B);
        const uint32_t bB = bBase0 + (uint32_t)((it & 1) * STAGE_B);
#pragma unroll
        for (int kk = 0; kk < BK; kk += 16) {
            uint32_t a[2][4], bb[4][4];
#pragma unroll
            for (int mt = 0; mt < 2; mt++) {
                uint32_t addr = aB + (uint32_t)((aRow + mt * 16) * (STR * 2) + kk * 2 + aColB);
                asm volatile(
                    "ldmatrix.sync.aligned.m8n8.x4.shared.b16 {%0,%1,%2,%3}, [%4];"
                    : "=r"(a[mt][0]), "=r"(a[mt][1]), "=r"(a[mt][2]), "=r"(a[mt][3])
                    : "r"(addr));
            }
#pragma unroll
            for (int np = 0; np < 4; np++) {
                uint32_t addr = bB + (uint32_t)((bRow + np * 16) * (STR * 2) + kk * 2 + bColB);
                asm volatile(
                    "ldmatrix.sync.aligned.m8n8.x4.shared.b16 {%0,%1,%2,%3}, [%4];"
                    : "=r"(bb[np][0]), "=r"(bb[np][1]), "=r"(bb[np][2]), "=r"(bb[np][3])
                    : "r"(addr));
            }
#pragma unroll
            for (int mt = 0; mt < 2; mt++)
#pragma unroll
                for (int nt = 0; nt < 8; nt++) {
                    int np = nt >> 1, hi = nt & 1;
                    uint32_t b0 = bb[np][hi ? 2 : 0], b1 = bb[np][hi ? 3 : 1];
                    asm volatile(
                        "mma.sync.aligned.m16n8k16.row.col.f32.bf16.bf16.f32 "
                        "{%0,%1,%2,%3},{%4,%5,%6,%7},{%8,%9},{%0,%1,%2,%3};"
                        : "+f"(acc[mt][nt][0]), "+f"(acc[mt][nt][1]),
                          "+f"(acc[mt][nt][2]), "+f"(acc[mt][nt][3])
                        : "r"(a[mt][0]), "r"(a[mt][1]), "r"(a[mt][2]), "r"(a[mt][3]),
                          "r"(b0), "r"(b1));
                }
        }
        __syncthreads();
    }

    // ---- fused epilogue ----
    int* labI = (int*)dyn;
    int* labJ = labI + 128;
    if (tid < 128) { labI[tid] = g_lab[iBase + tid]; labJ[tid] = g_lab[jBase + tid]; }
    __syncthreads();

    float colE[16], colP[16];
#pragma unroll
    for (int c = 0; c < 16; c++) { colE[c] = 0.f; colP[c] = 0.f; }

#pragma unroll
    for (int mt = 0; mt < 2; mt++) {
#pragma unroll
        for (int h = 0; h < 2; h++) {
            int iLoc = wm * 32 + mt * 16 + qr + h * 8;
            int gi = iBase + iLoc;
            int li = labI[iLoc];
            float rE = 0.f, rP = 0.f;
#pragma unroll
            for (int nt = 0; nt < 8; nt++) {
#pragma unroll
                for (int cc = 0; cc < 2; cc++) {
                    int jLoc = wn * 64 + nt * 8 + qc * 2 + cc;
                    int gj = jBase + jLoc;
                    float s = acc[mt][nt][h * 2 + cc];
                    if (gi != gj) {
                        float e = __expf(s);
                        float ps = (li == labJ[jLoc]) ? s : 0.f;
                        rE += e; rP += ps;
                        if (!diagTile) { colE[nt * 2 + cc] += e; colP[nt * 2 + cc] += ps; }
                    }
                }
            }
            // reduce over qc (4 lanes share a row)
            rE += __shfl_xor_sync(0xffffffffu, rE, 1);
            rE += __shfl_xor_sync(0xffffffffu, rE, 2);
            rP += __shfl_xor_sync(0xffffffffu, rP, 1);
            rP += __shfl_xor_sync(0xffffffffu, rP, 2);
            if (qc == 0) {
                atomicAdd(&g_S[gi], rE);
                atomicAdd(&g_P[gi], rP);
            }
        }
    }

    if (!diagTile) {
        // mirrored contributions: sim_ji = sim_ij -> reduce over qr (8 lanes/col)
#pragma unroll
        for (int nt = 0; nt < 8; nt++) {
#pragma unroll
            for (int cc = 0; cc < 2; cc++) {
                float e = colE[nt * 2 + cc], p = colP[nt * 2 + cc];
                e += __shfl_xor_sync(0xffffffffu, e, 4);
                e += __shfl_xor_sync(0xffffffffu, e, 8);
                e += __shfl_xor_sync(0xffffffffu, e, 16);
                p += __shfl_xor_sync(0xffffffffu, p, 4);
                p += __shfl_xor_sync(0xffffffffu, p, 8);
                p += __shfl_xor_sync(0xffffffffu, p, 16);
                if (lane < 4) {
                    int gj = jBase + wn * 64 + nt * 8 + lane * 2 + cc;
                    atomicAdd(&g_S[gj], e);
                    atomicAdd(&g_P[gj], p);
                }
            }
        }
    }
}

// ---------------------------------------------------------------------------
// Final: label histogram (smem) + per-row loss + mean.
__global__ void fin_kernel(float* __restrict__ out) {
    __shared__ float sm[512];
    __shared__ int cnt[128];
    int tid = threadIdx.x;
    if (tid < 128) cnt[tid] = 0;
    __syncthreads();
    for (int i = tid; i < NN; i += 512) atomicAdd(&cnt[g_lab[i] & 127], 1);
    __syncthreads();
    float s = 0.f;
    for (int i = tid; i < NN; i += 512) {
        float C = (float)(cnt[g_lab[i] & 127] - 1);
        float v = (g_P[i] - C * logf(g_S[i])) / (C + 1e-8f);
        s += v;
    }
    sm[tid] = s;
    __syncthreads();
    for (int st = 256; st; st >>= 1) {
        if (tid < st) sm[tid] += sm[tid + st];
        __syncthreads();
    }
    if (tid == 0) out[0] = -sm[0] / (float)NN;
}

// ---------------------------------------------------------------------------
extern "C" void kernel_launch(void* const* d_in, const int* in_sizes, int n_in,
                              void* d_out, int out_size) {
    const float* features = (const float*)d_in[0];
    const int* labels32 = (const int*)d_in[1];   // int32 view; layout auto-detected
    float* out = (float*)d_out;

    cudaFuncSetAttribute(gemm_kernel,
                         cudaFuncAttributeMaxDynamicSharedMemorySize, SMEM_DYN);

    norm_kernel<<<NN, 128>>>(features, labels32);
    gemm_kernel<<<NBLK, 256, SMEM_DYN>>>();
    fin_kernel<<<1, 512>>>(out);
}